// round 2
// baseline (speedup 1.0000x reference)
#include <cuda_runtime.h>
#include <cuda_bf16.h>
#include <cstdint>

// ---------------------------------------------------------------------------
// Problem constants
// ---------------------------------------------------------------------------
#define ROWS_TOTAL 50176        // 256*14*14
#define KDIM       384
#define NDIM       1536
#define M_TILE     128
#define N_TILE     128
#define K_CHUNK    32
#define NUM_KC     (KDIM / K_CHUNK)   // 12
#define STAGES     4
#define LN_EPS     1e-6f

// bf16 hi/lo split scratch (no cudaMalloc allowed -> __device__ globals)
__device__ __nv_bfloat16 g_xhi[(size_t)ROWS_TOTAL * KDIM];
__device__ __nv_bfloat16 g_xlo[(size_t)ROWS_TOTAL * KDIM];
__device__ __nv_bfloat16 g_whi[(size_t)NDIM * KDIM];
__device__ __nv_bfloat16 g_wlo[(size_t)NDIM * KDIM];

// ---------------------------------------------------------------------------
// Inline PTX (baseline sm_80-class features only: ldmatrix / mma.sync / cp.async)
// ---------------------------------------------------------------------------
__device__ __forceinline__ uint32_t smem_u32(const void* p) {
    uint32_t a;
    asm("{ .reg .u64 t; cvta.to.shared.u64 t, %1; cvt.u32.u64 %0, t; }"
        : "=r"(a) : "l"(p));
    return a;
}

#define CP_ASYNC16(saddr, gptr) \
    asm volatile("cp.async.cg.shared.global [%0], [%1], 16;" \
                 :: "r"(saddr), "l"(gptr))

#define CP_COMMIT() asm volatile("cp.async.commit_group;")

#define CP_WAIT(n) asm volatile("cp.async.wait_group %0;" :: "n"(n))

#define LDSM_X4(r, addr) \
    asm volatile("ldmatrix.sync.aligned.m8n8.x4.shared.b16 {%0,%1,%2,%3}, [%4];" \
                 : "=r"((r)[0]), "=r"((r)[1]), "=r"((r)[2]), "=r"((r)[3]) \
                 : "r"(addr))

#define MMA16816(c, a, b0v, b1v) \
    asm volatile("mma.sync.aligned.m16n8k16.row.col.f32.bf16.bf16.f32 " \
                 "{%0,%1,%2,%3}, {%4,%5,%6,%7}, {%8,%9}, {%0,%1,%2,%3};" \
                 : "+f"((c)[0]), "+f"((c)[1]), "+f"((c)[2]), "+f"((c)[3]) \
                 : "r"((a)[0]), "r"((a)[1]), "r"((a)[2]), "r"((a)[3]), \
                   "r"(b0v), "r"(b1v))

// ---------------------------------------------------------------------------
// SMEM layout for GEMM (per stage): padded rows of 40 bf16 (80 B) -> conflict-free
//   A_hi [128][40] | A_lo | B_hi | B_lo
// ---------------------------------------------------------------------------
#define ROW_B      80                      // bytes per padded smem row
#define TILE_B     (M_TILE * ROW_B)        // 10240
#define OFF_AHI    0
#define OFF_ALO    (1 * TILE_B)
#define OFF_BHI    (2 * TILE_B)
#define OFF_BLO    (3 * TILE_B)
#define STAGE_B    (4 * TILE_B)            // 40960
#define SMEM_TOTAL (STAGES * STAGE_B)      // 163840

__device__ __forceinline__ float gelu_exact(float v) {
    return 0.5f * v * (1.0f + erff(v * 0.70710678118654752f));
}

// ---------------------------------------------------------------------------
// Kernel 1: LayerNorm (stats + apply) and bf16 hi/lo split of X
// One warp per row (384 cols = 3 float4 per lane)
// ---------------------------------------------------------------------------
__global__ __launch_bounds__(256) void ln_split_kernel(
    const float* __restrict__ x,
    const float* __restrict__ gamma,
    const float* __restrict__ beta)
{
    int row  = blockIdx.x * 8 + (threadIdx.x >> 5);
    int lane = threadIdx.x & 31;
    const float4* xr = reinterpret_cast<const float4*>(x + (size_t)row * KDIM);

    float4 v[3];
    float s = 0.f, ss = 0.f;
#pragma unroll
    for (int i = 0; i < 3; i++) {
        v[i] = xr[lane + i * 32];
        s  += v[i].x + v[i].y + v[i].z + v[i].w;
        ss += v[i].x * v[i].x + v[i].y * v[i].y + v[i].z * v[i].z + v[i].w * v[i].w;
    }
#pragma unroll
    for (int o = 16; o > 0; o >>= 1) {
        s  += __shfl_xor_sync(0xffffffffu, s, o);
        ss += __shfl_xor_sync(0xffffffffu, ss, o);
    }
    float mu  = s * (1.0f / KDIM);
    float var = ss * (1.0f / KDIM) - mu * mu;
    float rs  = rsqrtf(var + LN_EPS);

#pragma unroll
    for (int i = 0; i < 3; i++) {
        int col = (lane + i * 32) * 4;
        float4 gv = *reinterpret_cast<const float4*>(gamma + col);
        float4 bv = *reinterpret_cast<const float4*>(beta + col);
        float n0 = fmaf(v[i].x - mu, rs * gv.x, bv.x);
        float n1 = fmaf(v[i].y - mu, rs * gv.y, bv.y);
        float n2 = fmaf(v[i].z - mu, rs * gv.z, bv.z);
        float n3 = fmaf(v[i].w - mu, rs * gv.w, bv.w);

        __nv_bfloat16 h0 = __float2bfloat16_rn(n0);
        __nv_bfloat16 h1 = __float2bfloat16_rn(n1);
        __nv_bfloat16 h2 = __float2bfloat16_rn(n2);
        __nv_bfloat16 h3 = __float2bfloat16_rn(n3);
        __nv_bfloat16 l0 = __float2bfloat16_rn(n0 - __bfloat162float(h0));
        __nv_bfloat16 l1 = __float2bfloat16_rn(n1 - __bfloat162float(h1));
        __nv_bfloat16 l2 = __float2bfloat16_rn(n2 - __bfloat162float(h2));
        __nv_bfloat16 l3 = __float2bfloat16_rn(n3 - __bfloat162float(h3));

        __nv_bfloat162* ph = reinterpret_cast<__nv_bfloat162*>(g_xhi + (size_t)row * KDIM + col);
        ph[0] = __nv_bfloat162(h0, h1);
        ph[1] = __nv_bfloat162(h2, h3);
        __nv_bfloat162* pl = reinterpret_cast<__nv_bfloat162*>(g_xlo + (size_t)row * KDIM + col);
        pl[0] = __nv_bfloat162(l0, l1);
        pl[1] = __nv_bfloat162(l2, l3);
    }
}

// ---------------------------------------------------------------------------
// Kernel 2: split W into bf16 hi/lo
// ---------------------------------------------------------------------------
__global__ __launch_bounds__(256) void w_split_kernel(const float* __restrict__ W) {
    int idx = (blockIdx.x * 256 + threadIdx.x) * 4;   // 1536*384 = 589824, /4 = 147456 threads
    float4 wv = *reinterpret_cast<const float4*>(W + idx);
    __nv_bfloat16 h0 = __float2bfloat16_rn(wv.x);
    __nv_bfloat16 h1 = __float2bfloat16_rn(wv.y);
    __nv_bfloat16 h2 = __float2bfloat16_rn(wv.z);
    __nv_bfloat16 h3 = __float2bfloat16_rn(wv.w);
    __nv_bfloat16 l0 = __float2bfloat16_rn(wv.x - __bfloat162float(h0));
    __nv_bfloat16 l1 = __float2bfloat16_rn(wv.y - __bfloat162float(h1));
    __nv_bfloat16 l2 = __float2bfloat16_rn(wv.z - __bfloat162float(h2));
    __nv_bfloat16 l3 = __float2bfloat16_rn(wv.w - __bfloat162float(h3));
    __nv_bfloat162* ph = reinterpret_cast<__nv_bfloat162*>(g_whi + idx);
    ph[0] = __nv_bfloat162(h0, h1);
    ph[1] = __nv_bfloat162(h2, h3);
    __nv_bfloat162* pl = reinterpret_cast<__nv_bfloat162*>(g_wlo + idx);
    pl[0] = __nv_bfloat162(l0, l1);
    pl[1] = __nv_bfloat162(l2, l3);
}

// ---------------------------------------------------------------------------
// Kernel 3: bf16 GEMM (3-term hi/lo) + bias + exact GELU epilogue
// 256 threads = 8 warps; warp grid 2(M) x 4(N); warp tile 64x32
// ---------------------------------------------------------------------------
__device__ __forceinline__ void load_stage(
    uint32_t sbase, int m0, int n0, int k0, int tid)
{
    const __nv_bfloat16* xhi = g_xhi;
    const __nv_bfloat16* xlo = g_xlo;
    const __nv_bfloat16* whi = g_whi;
    const __nv_bfloat16* wlo = g_wlo;
#pragma unroll
    for (int i = 0; i < 2; i++) {
        int idx = tid + i * 256;        // 512 chunks of 16B per operand tile
        int r = idx >> 2;               // row 0..127
        int c = idx & 3;                // 16B chunk in row
        size_t ga = (size_t)(m0 + r) * KDIM + k0 + c * 8;
        size_t gb = (size_t)(n0 + r) * KDIM + k0 + c * 8;
        uint32_t so = (uint32_t)(r * ROW_B + c * 16);
        CP_ASYNC16(sbase + OFF_AHI + so, xhi + ga);
        CP_ASYNC16(sbase + OFF_ALO + so, xlo + ga);
        CP_ASYNC16(sbase + OFF_BHI + so, whi + gb);
        CP_ASYNC16(sbase + OFF_BLO + so, wlo + gb);
    }
}

__global__ __launch_bounds__(256, 1) void gemm_kernel(
    const float* __restrict__ bias,
    float* __restrict__ out)
{
    extern __shared__ char smem[];
    const uint32_t smem_base = smem_u32(smem);

    const int tid    = threadIdx.x;
    const int wid    = tid >> 5;
    const int lane   = tid & 31;
    const int warp_m = wid & 1;         // 0..1  (64-row halves)
    const int warp_n = wid >> 1;        // 0..3  (32-col quarters)

    const int n0 = blockIdx.x * N_TILE; // n fastest -> X tile L2 reuse
    const int m0 = blockIdx.y * M_TILE;

    // prologue: prefetch STAGES-1 stages
#pragma unroll
    for (int s = 0; s < STAGES - 1; s++) {
        load_stage(smem_base + s * STAGE_B, m0, n0, s * K_CHUNK, tid);
        CP_COMMIT();
    }

    float acc[4][4][4];
#pragma unroll
    for (int a = 0; a < 4; a++)
#pragma unroll
        for (int b = 0; b < 4; b++)
#pragma unroll
            for (int c = 0; c < 4; c++) acc[a][b][c] = 0.f;

    const int lrow = lane & 15;
    const int lsel = lane >> 4;

    for (int kc = 0; kc < NUM_KC; kc++) {
        CP_WAIT(STAGES - 2);
        __syncthreads();

        if (kc + STAGES - 1 < NUM_KC)
            load_stage(smem_base + ((kc + STAGES - 1) & (STAGES - 1)) * STAGE_B,
                       m0, n0, (kc + STAGES - 1) * K_CHUNK, tid);
        CP_COMMIT();

        const uint32_t st = smem_base + (kc & (STAGES - 1)) * STAGE_B;
#pragma unroll
        for (int ks = 0; ks < 2; ks++) {     // two k16 steps per 32-chunk
            uint32_t ahi[4][4], alo[4][4], bhi[2][4], blo[2][4];
#pragma unroll
            for (int mf = 0; mf < 4; mf++) {
                uint32_t ad = st + OFF_AHI +
                              (uint32_t)((warp_m * 64 + mf * 16 + lrow) * ROW_B + ks * 32 + lsel * 16);
                LDSM_X4(ahi[mf], ad);
                LDSM_X4(alo[mf], ad + (OFF_ALO - OFF_AHI));
            }
#pragma unroll
            for (int nf2 = 0; nf2 < 2; nf2++) {
                uint32_t bd = st + OFF_BHI +
                              (uint32_t)((warp_n * 32 + nf2 * 16 + lrow) * ROW_B + ks * 32 + lsel * 16);
                LDSM_X4(bhi[nf2], bd);
                LDSM_X4(blo[nf2], bd + (OFF_BLO - OFF_BHI));
            }
#pragma unroll
            for (int mf = 0; mf < 4; mf++) {
#pragma unroll
                for (int nf = 0; nf < 4; nf++) {
                    const int n2 = nf >> 1, sel = nf & 1;
                    MMA16816(acc[mf][nf], ahi[mf], bhi[n2][sel], bhi[n2][sel + 2]);
                    MMA16816(acc[mf][nf], ahi[mf], blo[n2][sel], blo[n2][sel + 2]);
                    MMA16816(acc[mf][nf], alo[mf], bhi[n2][sel], bhi[n2][sel + 2]);
                }
            }
        }
    }

    // epilogue: bias + exact GELU, direct stores (each 32B sector fully covered)
    const int tg = lane & 3, gp = lane >> 2;
#pragma unroll
    for (int mf = 0; mf < 4; mf++) {
#pragma unroll
        for (int nf = 0; nf < 4; nf++) {
            int row = m0 + warp_m * 64 + mf * 16 + gp;
            int col = n0 + warp_n * 32 + nf * 8 + tg * 2;
            float2 bv = *reinterpret_cast<const float2*>(bias + col);
            float2 o0, o1;
            o0.x = gelu_exact(acc[mf][nf][0] + bv.x);
            o0.y = gelu_exact(acc[mf][nf][1] + bv.y);
            o1.x = gelu_exact(acc[mf][nf][2] + bv.x);
            o1.y = gelu_exact(acc[mf][nf][3] + bv.y);
            *reinterpret_cast<float2*>(out + (size_t)row * NDIM + col) = o0;
            *reinterpret_cast<float2*>(out + (size_t)(row + 8) * NDIM + col) = o1;
        }
    }
}

// ---------------------------------------------------------------------------
// Launch
// ---------------------------------------------------------------------------
extern "C" void kernel_launch(void* const* d_in, const int* in_sizes, int n_in,
                              void* d_out, int out_size) {
    const float* x     = (const float*)d_in[0];
    const float* gamma = (const float*)d_in[1];
    const float* beta  = (const float*)d_in[2];
    const float* W     = (const float*)d_in[3];
    const float* b     = (const float*)d_in[4];
    float* out = (float*)d_out;

    ln_split_kernel<<<ROWS_TOTAL / 8, 256>>>(x, gamma, beta);
    w_split_kernel<<<(NDIM * KDIM) / 1024, 256>>>(W);

    cudaFuncSetAttribute(gemm_kernel,
                         cudaFuncAttributeMaxDynamicSharedMemorySize, SMEM_TOTAL);
    dim3 grid(NDIM / N_TILE, ROWS_TOTAL / M_TILE);   // (12, 392)
    gemm_kernel<<<grid, 256, SMEM_TOTAL>>>(b, out);
}

// round 3
// speedup vs baseline: 1.6313x; 1.6313x over previous
#include <cuda_runtime.h>
#include <cuda_fp16.h>
#include <cstdint>

// ---------------------------------------------------------------------------
// Problem constants
// ---------------------------------------------------------------------------
#define ROWS_TOTAL 50176        // 256*14*14
#define KDIM       384
#define NDIM       1536
#define M_TILE     128
#define N_TILE     128
#define K_CHUNK    32
#define NUM_KC     (KDIM / K_CHUNK)   // 12
#define STAGES     3
#define LN_EPS     1e-6f

// fp16 scratch (no cudaMalloc allowed -> __device__ globals)
__device__ __half g_xh[(size_t)ROWS_TOTAL * KDIM];   // LN-applied X, fp16
__device__ __half g_wh[(size_t)NDIM * KDIM];         // W hi
__device__ __half g_wl[(size_t)NDIM * KDIM];         // W lo (residual)

// ---------------------------------------------------------------------------
// Inline PTX (baseline features only: ldmatrix / mma.sync / cp.async)
// ---------------------------------------------------------------------------
__device__ __forceinline__ uint32_t smem_u32(const void* p) {
    uint32_t a;
    asm("{ .reg .u64 t; cvta.to.shared.u64 t, %1; cvt.u32.u64 %0, t; }"
        : "=r"(a) : "l"(p));
    return a;
}

#define CP_ASYNC16(saddr, gptr) \
    asm volatile("cp.async.cg.shared.global [%0], [%1], 16;" \
                 :: "r"(saddr), "l"(gptr))

#define CP_COMMIT() asm volatile("cp.async.commit_group;")
#define CP_WAIT(n)  asm volatile("cp.async.wait_group %0;" :: "n"(n))

#define LDSM_X4(r, addr) \
    asm volatile("ldmatrix.sync.aligned.m8n8.x4.shared.b16 {%0,%1,%2,%3}, [%4];" \
                 : "=r"((r)[0]), "=r"((r)[1]), "=r"((r)[2]), "=r"((r)[3]) \
                 : "r"(addr))

#define MMA16816(c, a, b0v, b1v) \
    asm volatile("mma.sync.aligned.m16n8k16.row.col.f32.f16.f16.f32 " \
                 "{%0,%1,%2,%3}, {%4,%5,%6,%7}, {%8,%9}, {%0,%1,%2,%3};" \
                 : "+f"((c)[0]), "+f"((c)[1]), "+f"((c)[2]), "+f"((c)[3]) \
                 : "r"((a)[0]), "r"((a)[1]), "r"((a)[2]), "r"((a)[3]), \
                   "r"(b0v), "r"(b1v))

// ---------------------------------------------------------------------------
// SMEM: per stage { A [128][40] | B_hi [128][40] | B_lo [128][40] }, 80B rows
// ---------------------------------------------------------------------------
#define ROW_B      80
#define TILE_B     (M_TILE * ROW_B)       // 10240
#define OFF_A      0
#define OFF_BH     (1 * TILE_B)
#define OFF_BL     (2 * TILE_B)
#define STAGE_B    (3 * TILE_B)           // 30720
#define SMEM_TOTAL (STAGES * STAGE_B)     // 92160  -> 2 CTAs/SM

__device__ __forceinline__ float gelu_exact(float v) {
    return 0.5f * v * (1.0f + erff(v * 0.70710678118654752f));
}

// ---------------------------------------------------------------------------
// Kernel 1: LayerNorm (stats + apply) -> fp16 X
// ---------------------------------------------------------------------------
__global__ __launch_bounds__(256) void ln_kernel(
    const float* __restrict__ x,
    const float* __restrict__ gamma,
    const float* __restrict__ beta)
{
    int row  = blockIdx.x * 8 + (threadIdx.x >> 5);
    int lane = threadIdx.x & 31;
    const float4* xr = reinterpret_cast<const float4*>(x + (size_t)row * KDIM);

    float4 v[3];
    float s = 0.f, ss = 0.f;
#pragma unroll
    for (int i = 0; i < 3; i++) {
        v[i] = xr[lane + i * 32];
        s  += v[i].x + v[i].y + v[i].z + v[i].w;
        ss += v[i].x * v[i].x + v[i].y * v[i].y + v[i].z * v[i].z + v[i].w * v[i].w;
    }
#pragma unroll
    for (int o = 16; o > 0; o >>= 1) {
        s  += __shfl_xor_sync(0xffffffffu, s, o);
        ss += __shfl_xor_sync(0xffffffffu, ss, o);
    }
    float mu  = s * (1.0f / KDIM);
    float var = ss * (1.0f / KDIM) - mu * mu;
    float rs  = rsqrtf(var + LN_EPS);

#pragma unroll
    for (int i = 0; i < 3; i++) {
        int col = (lane + i * 32) * 4;
        float4 gv = *reinterpret_cast<const float4*>(gamma + col);
        float4 bv = *reinterpret_cast<const float4*>(beta + col);
        float n0 = fmaf(v[i].x - mu, rs * gv.x, bv.x);
        float n1 = fmaf(v[i].y - mu, rs * gv.y, bv.y);
        float n2 = fmaf(v[i].z - mu, rs * gv.z, bv.z);
        float n3 = fmaf(v[i].w - mu, rs * gv.w, bv.w);

        __half2* p = reinterpret_cast<__half2*>(g_xh + (size_t)row * KDIM + col);
        p[0] = __half2(__float2half_rn(n0), __float2half_rn(n1));
        p[1] = __half2(__float2half_rn(n2), __float2half_rn(n3));
    }
}

// ---------------------------------------------------------------------------
// Kernel 2: split W -> fp16 hi + lo
// ---------------------------------------------------------------------------
__global__ __launch_bounds__(256) void w_split_kernel(const float* __restrict__ W) {
    int idx = (blockIdx.x * 256 + threadIdx.x) * 4;
    float4 wv = *reinterpret_cast<const float4*>(W + idx);
    __half h0 = __float2half_rn(wv.x);
    __half h1 = __float2half_rn(wv.y);
    __half h2 = __float2half_rn(wv.z);
    __half h3 = __float2half_rn(wv.w);
    __half l0 = __float2half_rn(wv.x - __half2float(h0));
    __half l1 = __float2half_rn(wv.y - __half2float(h1));
    __half l2 = __float2half_rn(wv.z - __half2float(h2));
    __half l3 = __float2half_rn(wv.w - __half2float(h3));
    __half2* ph = reinterpret_cast<__half2*>(g_wh + idx);
    ph[0] = __half2(h0, h1);
    ph[1] = __half2(h2, h3);
    __half2* pl = reinterpret_cast<__half2*>(g_wl + idx);
    pl[0] = __half2(l0, l1);
    pl[1] = __half2(l2, l3);
}

// ---------------------------------------------------------------------------
// Kernel 3: fp16 GEMM (2-term: Xh*Wh + Xh*Wl) + bias + exact GELU
// 256 threads = 8 warps; warp grid 2(M) x 4(N); warp tile 64x32
// ---------------------------------------------------------------------------
__device__ __forceinline__ void load_stage(
    uint32_t sbase, int m0, int n0, int k0, int tid)
{
#pragma unroll
    for (int i = 0; i < 2; i++) {
        int idx = tid + i * 256;        // 512 x 16B chunks per tile
        int r = idx >> 2;
        int c = idx & 3;
        size_t ga = (size_t)(m0 + r) * KDIM + k0 + c * 8;
        size_t gb = (size_t)(n0 + r) * KDIM + k0 + c * 8;
        uint32_t so = (uint32_t)(r * ROW_B + c * 16);
        CP_ASYNC16(sbase + OFF_A  + so, g_xh + ga);
        CP_ASYNC16(sbase + OFF_BH + so, g_wh + gb);
        CP_ASYNC16(sbase + OFF_BL + so, g_wl + gb);
    }
}

__global__ __launch_bounds__(256, 2) void gemm_kernel(
    const float* __restrict__ bias,
    float* __restrict__ out)
{
    extern __shared__ char smem[];
    const uint32_t smem_base = smem_u32(smem);

    const int tid    = threadIdx.x;
    const int wid    = tid >> 5;
    const int lane   = tid & 31;
    const int warp_m = wid & 1;
    const int warp_n = wid >> 1;

    const int n0 = blockIdx.x * N_TILE;
    const int m0 = blockIdx.y * M_TILE;

    // prologue: prefetch 2 stages
#pragma unroll
    for (int s = 0; s < STAGES - 1; s++) {
        load_stage(smem_base + s * STAGE_B, m0, n0, s * K_CHUNK, tid);
        CP_COMMIT();
    }

    float acc[4][4][4];
#pragma unroll
    for (int a = 0; a < 4; a++)
#pragma unroll
        for (int b = 0; b < 4; b++)
#pragma unroll
            for (int c = 0; c < 4; c++) acc[a][b][c] = 0.f;

    const int lrow = lane & 15;
    const int lsel = lane >> 4;

    int sread = 0, swrite = STAGES - 1;

    for (int kc = 0; kc < NUM_KC; kc++) {
        CP_WAIT(STAGES - 2);
        __syncthreads();

        if (kc + STAGES - 1 < NUM_KC)
            load_stage(smem_base + swrite * STAGE_B, m0, n0,
                       (kc + STAGES - 1) * K_CHUNK, tid);
        CP_COMMIT();
        if (++swrite == STAGES) swrite = 0;

        const uint32_t st = smem_base + sread * STAGE_B;
        if (++sread == STAGES) sread = 0;

#pragma unroll
        for (int ks = 0; ks < 2; ks++) {
            uint32_t af[4][4], bh[2][4], bl[2][4];
#pragma unroll
            for (int mf = 0; mf < 4; mf++) {
                uint32_t ad = st + OFF_A +
                    (uint32_t)((warp_m * 64 + mf * 16 + lrow) * ROW_B + ks * 32 + lsel * 16);
                LDSM_X4(af[mf], ad);
            }
#pragma unroll
            for (int nf2 = 0; nf2 < 2; nf2++) {
                uint32_t bd = st + OFF_BH +
                    (uint32_t)((warp_n * 32 + nf2 * 16 + lrow) * ROW_B + ks * 32 + lsel * 16);
                LDSM_X4(bh[nf2], bd);
                LDSM_X4(bl[nf2], bd + (OFF_BL - OFF_BH));
            }
#pragma unroll
            for (int mf = 0; mf < 4; mf++) {
#pragma unroll
                for (int nf = 0; nf < 4; nf++) {
                    const int n2 = nf >> 1, sel = nf & 1;
                    MMA16816(acc[mf][nf], af[mf], bh[n2][sel], bh[n2][sel + 2]);
                    MMA16816(acc[mf][nf], af[mf], bl[n2][sel], bl[n2][sel + 2]);
                }
            }
        }
    }

    // epilogue: bias + exact GELU, direct float2 stores (sectors fully covered)
    const int tg = lane & 3, gp = lane >> 2;
#pragma unroll
    for (int mf = 0; mf < 4; mf++) {
#pragma unroll
        for (int nf = 0; nf < 4; nf++) {
            int row = m0 + warp_m * 64 + mf * 16 + gp;
            int col = n0 + warp_n * 32 + nf * 8 + tg * 2;
            float2 bv = *reinterpret_cast<const float2*>(bias + col);
            float2 o0, o1;
            o0.x = gelu_exact(acc[mf][nf][0] + bv.x);
            o0.y = gelu_exact(acc[mf][nf][1] + bv.y);
            o1.x = gelu_exact(acc[mf][nf][2] + bv.x);
            o1.y = gelu_exact(acc[mf][nf][3] + bv.y);
            *reinterpret_cast<float2*>(out + (size_t)row * NDIM + col) = o0;
            *reinterpret_cast<float2*>(out + (size_t)(row + 8) * NDIM + col) = o1;
        }
    }
}

// ---------------------------------------------------------------------------
// Launch
// ---------------------------------------------------------------------------
extern "C" void kernel_launch(void* const* d_in, const int* in_sizes, int n_in,
                              void* d_out, int out_size) {
    const float* x     = (const float*)d_in[0];
    const float* gamma = (const float*)d_in[1];
    const float* beta  = (const float*)d_in[2];
    const float* W     = (const float*)d_in[3];
    const float* b     = (const float*)d_in[4];
    float* out = (float*)d_out;

    ln_kernel<<<ROWS_TOTAL / 8, 256>>>(x, gamma, beta);
    w_split_kernel<<<(NDIM * KDIM) / 1024, 256>>>(W);

    cudaFuncSetAttribute(gemm_kernel,
                         cudaFuncAttributeMaxDynamicSharedMemorySize, SMEM_TOTAL);
    dim3 grid(NDIM / N_TILE, ROWS_TOTAL / M_TILE);   // (12, 392)
    gemm_kernel<<<grid, 256, SMEM_TOTAL>>>(b, out);
}

// round 4
// speedup vs baseline: 2.5025x; 1.5341x over previous
#include <cuda_runtime.h>
#include <cuda_fp16.h>
#include <cstdint>

// ---------------------------------------------------------------------------
// Problem constants
// ---------------------------------------------------------------------------
#define ROWS_TOTAL 50176        // 256*14*14
#define KDIM       384
#define NDIM       1536
#define M_TILE     128
#define N_TILE     128
#define K_CHUNK    32
#define NUM_KC     (KDIM / K_CHUNK)   // 12
#define STAGES     4
#define LN_EPS     1e-6f

// fp16 scratch (no cudaMalloc allowed -> __device__ globals)
__device__ __half g_xh[(size_t)ROWS_TOTAL * KDIM];   // LN-applied X, fp16
__device__ __half g_wh[(size_t)NDIM * KDIM];         // W, fp16

// ---------------------------------------------------------------------------
// Inline PTX (baseline features only: ldmatrix / mma.sync / cp.async)
// ---------------------------------------------------------------------------
__device__ __forceinline__ uint32_t smem_u32(const void* p) {
    uint32_t a;
    asm("{ .reg .u64 t; cvta.to.shared.u64 t, %1; cvt.u32.u64 %0, t; }"
        : "=r"(a) : "l"(p));
    return a;
}

#define CP_ASYNC16(saddr, gptr) \
    asm volatile("cp.async.cg.shared.global [%0], [%1], 16;" \
                 :: "r"(saddr), "l"(gptr))

#define CP_COMMIT() asm volatile("cp.async.commit_group;")
#define CP_WAIT(n)  asm volatile("cp.async.wait_group %0;" :: "n"(n))

#define LDSM_X4(r, addr) \
    asm volatile("ldmatrix.sync.aligned.m8n8.x4.shared.b16 {%0,%1,%2,%3}, [%4];" \
                 : "=r"((r)[0]), "=r"((r)[1]), "=r"((r)[2]), "=r"((r)[3]) \
                 : "r"(addr))

#define MMA16816(c, a, b0v, b1v) \
    asm volatile("mma.sync.aligned.m16n8k16.row.col.f32.f16.f16.f32 " \
                 "{%0,%1,%2,%3}, {%4,%5,%6,%7}, {%8,%9}, {%0,%1,%2,%3};" \
                 : "+f"((c)[0]), "+f"((c)[1]), "+f"((c)[2]), "+f"((c)[3]) \
                 : "r"((a)[0]), "r"((a)[1]), "r"((a)[2]), "r"((a)[3]), \
                   "r"(b0v), "r"(b1v))

// ---------------------------------------------------------------------------
// SMEM: per stage { A [128][40] | B [128][40] }, 80B padded rows (conflict-free)
// ---------------------------------------------------------------------------
#define ROW_B      80
#define TILE_B     (M_TILE * ROW_B)       // 10240
#define OFF_A      0
#define OFF_B      TILE_B
#define STAGE_B    (2 * TILE_B)           // 20480
#define SMEM_TOTAL (STAGES * STAGE_B)     // 81920 -> 2 CTAs/SM

__device__ __forceinline__ float gelu_exact(float v) {
    return 0.5f * v * (1.0f + erff(v * 0.70710678118654752f));
}

// ---------------------------------------------------------------------------
// Kernel 1: LayerNorm (stats + apply) -> fp16 X
// ---------------------------------------------------------------------------
__global__ __launch_bounds__(256) void ln_kernel(
    const float* __restrict__ x,
    const float* __restrict__ gamma,
    const float* __restrict__ beta)
{
    int row  = blockIdx.x * 8 + (threadIdx.x >> 5);
    int lane = threadIdx.x & 31;
    const float4* xr = reinterpret_cast<const float4*>(x + (size_t)row * KDIM);

    float4 v[3];
    float s = 0.f, ss = 0.f;
#pragma unroll
    for (int i = 0; i < 3; i++) {
        v[i] = xr[lane + i * 32];
        s  += v[i].x + v[i].y + v[i].z + v[i].w;
        ss += v[i].x * v[i].x + v[i].y * v[i].y + v[i].z * v[i].z + v[i].w * v[i].w;
    }
#pragma unroll
    for (int o = 16; o > 0; o >>= 1) {
        s  += __shfl_xor_sync(0xffffffffu, s, o);
        ss += __shfl_xor_sync(0xffffffffu, ss, o);
    }
    float mu  = s * (1.0f / KDIM);
    float var = ss * (1.0f / KDIM) - mu * mu;
    float rs  = rsqrtf(var + LN_EPS);

#pragma unroll
    for (int i = 0; i < 3; i++) {
        int col = (lane + i * 32) * 4;
        float4 gv = *reinterpret_cast<const float4*>(gamma + col);
        float4 bv = *reinterpret_cast<const float4*>(beta + col);
        float n0 = fmaf(v[i].x - mu, rs * gv.x, bv.x);
        float n1 = fmaf(v[i].y - mu, rs * gv.y, bv.y);
        float n2 = fmaf(v[i].z - mu, rs * gv.z, bv.z);
        float n3 = fmaf(v[i].w - mu, rs * gv.w, bv.w);

        __half2* p = reinterpret_cast<__half2*>(g_xh + (size_t)row * KDIM + col);
        p[0] = __half2(__float2half_rn(n0), __float2half_rn(n1));
        p[1] = __half2(__float2half_rn(n2), __float2half_rn(n3));
    }
}

// ---------------------------------------------------------------------------
// Kernel 2: convert W -> fp16
// ---------------------------------------------------------------------------
__global__ __launch_bounds__(256) void w_conv_kernel(const float* __restrict__ W) {
    int idx = (blockIdx.x * 256 + threadIdx.x) * 4;
    float4 wv = *reinterpret_cast<const float4*>(W + idx);
    __half2* p = reinterpret_cast<__half2*>(g_wh + idx);
    p[0] = __half2(__float2half_rn(wv.x), __float2half_rn(wv.y));
    p[1] = __half2(__float2half_rn(wv.z), __float2half_rn(wv.w));
}

// ---------------------------------------------------------------------------
// Kernel 3: fp16 GEMM + bias + exact GELU
// 256 threads = 8 warps; warp grid 2(M) x 4(N); warp tile 64x32
// ---------------------------------------------------------------------------
__device__ __forceinline__ void load_stage(
    uint32_t sbase, int m0, int n0, int k0, int tid)
{
#pragma unroll
    for (int i = 0; i < 2; i++) {
        int idx = tid + i * 256;        // 512 x 16B chunks per tile
        int r = idx >> 2;
        int c = idx & 3;
        size_t ga = (size_t)(m0 + r) * KDIM + k0 + c * 8;
        size_t gb = (size_t)(n0 + r) * KDIM + k0 + c * 8;
        uint32_t so = (uint32_t)(r * ROW_B + c * 16);
        CP_ASYNC16(sbase + OFF_A + so, g_xh + ga);
        CP_ASYNC16(sbase + OFF_B + so, g_wh + gb);
    }
}

__global__ __launch_bounds__(256, 2) void gemm_kernel(
    const float* __restrict__ bias,
    float* __restrict__ out)
{
    extern __shared__ char smem[];
    const uint32_t smem_base = smem_u32(smem);

    const int tid    = threadIdx.x;
    const int wid    = tid >> 5;
    const int lane   = tid & 31;
    const int warp_m = wid & 1;
    const int warp_n = wid >> 1;

    const int n0 = blockIdx.x * N_TILE;   // n fastest -> X-tile L2 reuse
    const int m0 = blockIdx.y * M_TILE;

    // prologue: prefetch STAGES-1 stages
#pragma unroll
    for (int s = 0; s < STAGES - 1; s++) {
        load_stage(smem_base + s * STAGE_B, m0, n0, s * K_CHUNK, tid);
        CP_COMMIT();
    }

    float acc[4][4][4];
#pragma unroll
    for (int a = 0; a < 4; a++)
#pragma unroll
        for (int b = 0; b < 4; b++)
#pragma unroll
            for (int c = 0; c < 4; c++) acc[a][b][c] = 0.f;

    const int lrow = lane & 15;
    const int lsel = lane >> 4;

    int sread = 0, swrite = STAGES - 1;

    for (int kc = 0; kc < NUM_KC; kc++) {
        CP_WAIT(STAGES - 2);
        __syncthreads();

        if (kc + STAGES - 1 < NUM_KC)
            load_stage(smem_base + swrite * STAGE_B, m0, n0,
                       (kc + STAGES - 1) * K_CHUNK, tid);
        CP_COMMIT();
        if (++swrite == STAGES) swrite = 0;

        const uint32_t st = smem_base + sread * STAGE_B;
        if (++sread == STAGES) sread = 0;

#pragma unroll
        for (int ks = 0; ks < 2; ks++) {
            uint32_t af[4][4], bf[2][4];
#pragma unroll
            for (int mf = 0; mf < 4; mf++) {
                uint32_t ad = st + OFF_A +
                    (uint32_t)((warp_m * 64 + mf * 16 + lrow) * ROW_B + ks * 32 + lsel * 16);
                LDSM_X4(af[mf], ad);
            }
#pragma unroll
            for (int nf2 = 0; nf2 < 2; nf2++) {
                uint32_t bd = st + OFF_B +
                    (uint32_t)((warp_n * 32 + nf2 * 16 + lrow) * ROW_B + ks * 32 + lsel * 16);
                LDSM_X4(bf[nf2], bd);
            }
#pragma unroll
            for (int mf = 0; mf < 4; mf++) {
#pragma unroll
                for (int nf = 0; nf < 4; nf++) {
                    const int n2 = nf >> 1, sel = nf & 1;
                    MMA16816(acc[mf][nf], af[mf], bf[n2][sel], bf[n2][sel + 2]);
                }
            }
        }
    }

    // epilogue: bias + exact GELU, direct float2 stores (sectors fully covered)
    const int tg = lane & 3, gp = lane >> 2;
#pragma unroll
    for (int mf = 0; mf < 4; mf++) {
#pragma unroll
        for (int nf = 0; nf < 4; nf++) {
            int row = m0 + warp_m * 64 + mf * 16 + gp;
            int col = n0 + warp_n * 32 + nf * 8 + tg * 2;
            float2 bv = *reinterpret_cast<const float2*>(bias + col);
            float2 o0, o1;
            o0.x = gelu_exact(acc[mf][nf][0] + bv.x);
            o0.y = gelu_exact(acc[mf][nf][1] + bv.y);
            o1.x = gelu_exact(acc[mf][nf][2] + bv.x);
            o1.y = gelu_exact(acc[mf][nf][3] + bv.y);
            *reinterpret_cast<float2*>(out + (size_t)row * NDIM + col) = o0;
            *reinterpret_cast<float2*>(out + (size_t)(row + 8) * NDIM + col) = o1;
        }
    }
}

// ---------------------------------------------------------------------------
// Launch
// ---------------------------------------------------------------------------
extern "C" void kernel_launch(void* const* d_in, const int* in_sizes, int n_in,
                              void* d_out, int out_size) {
    const float* x     = (const float*)d_in[0];
    const float* gamma = (const float*)d_in[1];
    const float* beta  = (const float*)d_in[2];
    const float* W     = (const float*)d_in[3];
    const float* b     = (const float*)d_in[4];
    float* out = (float*)d_out;

    ln_kernel<<<ROWS_TOTAL / 8, 256>>>(x, gamma, beta);
    w_conv_kernel<<<(NDIM * KDIM) / 1024, 256>>>(W);

    cudaFuncSetAttribute(gemm_kernel,
                         cudaFuncAttributeMaxDynamicSharedMemorySize, SMEM_TOTAL);
    dim3 grid(NDIM / N_TILE, ROWS_TOTAL / M_TILE);   // (12, 392)
    gemm_kernel<<<grid, 256, SMEM_TOTAL>>>(b, out);
}